// round 3
// baseline (speedup 1.0000x reference)
#include <cuda_runtime.h>
#include <cuda_bf16.h>
#include <math.h>

// Problem constants (fixed shapes for this dataset)
#define MUL  32
#define HID  64
#define NMAX 50000
#define EMAX 400000

// ---------------- static device scratch (no allocations allowed) ----------------
// scal layout: [4 regions r][E edges][32 m] ; scal column (r*32+m) of the MLP output
__device__ float g_scal[(size_t)4 * EMAX * 32];     // 204.8 MB
__device__ float g_agg[(size_t)NMAX * 256];         // per node: agg_s[64] + agg_v[64*3]
__device__ float g_gates[(size_t)NMAX * 64];        // sigmoid gates scratch
__device__ int   g_deg[NMAX];
__device__ int   g_rowptr[NMAX + 1];
__device__ int   g_cursor[NMAX];
__device__ int   g_eidx[EMAX];

__device__ __forceinline__ float4 ld4(const float* p) {
    return *reinterpret_cast<const float4*>(p);
}
__device__ __forceinline__ void st4(float* p, float4 v) {
    *reinterpret_cast<float4*>(p) = v;
}
__device__ __forceinline__ float sigmoidf_(float x) {
    return 1.0f / (1.0f + __expf(-x));
}
__device__ __forceinline__ float siluf_(float x) {
    return x * sigmoidf_(x);
}

// ---------------- CSR build ----------------
__global__ void zero_deg_kernel(int n) {
    int i = blockIdx.x * blockDim.x + threadIdx.x;
    if (i < n) g_deg[i] = 0;
}

__global__ void count_deg_kernel(const int* __restrict__ recv, int e) {
    int i = blockIdx.x * blockDim.x + threadIdx.x;
    if (i < e) atomicAdd(&g_deg[recv[i]], 1);
}

// single-block exclusive scan (Hillis-Steele over 1024-chunks with carry)
__global__ void scan_kernel(int n) {
    __shared__ int buf[1024];
    __shared__ int carry_s;
    int t = threadIdx.x;
    if (t == 0) carry_s = 0;
    __syncthreads();
    for (int base = 0; base < n; base += 1024) {
        int i = base + t;
        int v = (i < n) ? g_deg[i] : 0;
        buf[t] = v;
        __syncthreads();
        for (int off = 1; off < 1024; off <<= 1) {
            int x = (t >= off) ? buf[t - off] : 0;
            __syncthreads();
            buf[t] += x;
            __syncthreads();
        }
        int incl = buf[t];
        int excl = incl - v;
        int carry = carry_s;
        if (i < n) { g_rowptr[i] = carry + excl; g_cursor[i] = carry + excl; }
        __syncthreads();
        if (t == 1023) carry_s = carry + incl;
        __syncthreads();
    }
    if (t == 0) g_rowptr[n] = carry_s;
}

__global__ void scatter_kernel(const int* __restrict__ recv, int e) {
    int i = blockIdx.x * blockDim.x + threadIdx.x;
    if (i < e) {
        int pos = atomicAdd(&g_cursor[recv[i]], 1);
        g_eidx[pos] = i;
    }
}

// ---------------- edge kernel: 3-layer MLP -> scal[128] per edge ----------------
// dynamic smem layout (floats):
//   [0,64)      w1
//   [64,128)    b1
//   [128,192)   b2
//   [192,320)   b3
//   [320,4416)  w2  (64x64 row-major)
//   [4416,12608) w3 (64x128 row-major, as given)
#define E_OFF_W1  0
#define E_OFF_B1  64
#define E_OFF_B2  128
#define E_OFF_B3  192
#define E_OFF_W2  320
#define E_OFF_W3  4416
#define EDGE_SMEM_FLOATS 12608

__global__ __launch_bounds__(256) void edge_kernel(
    const float* __restrict__ norm,
    const float* __restrict__ w1, const float* __restrict__ b1,
    const float* __restrict__ w2, const float* __restrict__ b2,
    const float* __restrict__ w3, const float* __restrict__ b3,
    int E)
{
    extern __shared__ float sm[];
    for (int i = threadIdx.x; i < 64; i += blockDim.x) {
        sm[E_OFF_W1 + i] = w1[i];
        sm[E_OFF_B1 + i] = b1[i];
        sm[E_OFF_B2 + i] = b2[i];
    }
    for (int i = threadIdx.x; i < 128; i += blockDim.x) sm[E_OFF_B3 + i] = b3[i];
    for (int i = threadIdx.x; i < 4096; i += blockDim.x) sm[E_OFF_W2 + i] = w2[i];
    for (int i = threadIdx.x; i < 8192; i += blockDim.x) sm[E_OFF_W3 + i] = w3[i];
    __syncthreads();

    for (int e = blockIdx.x * blockDim.x + threadIdx.x; e < E;
         e += gridDim.x * blockDim.x) {
        float nv = norm[e];

        // h1 = silu(norm * w1 + b1)
        float h1[64];
#pragma unroll
        for (int j = 0; j < 64; j++)
            h1[j] = siluf_(nv * sm[E_OFF_W1 + j] + sm[E_OFF_B1 + j]);

        // h2 = silu(h1 @ w2 + b2)
        float h2[64];
#pragma unroll
        for (int jg = 0; jg < 16; jg++) {
            float4 acc = ld4(&sm[E_OFF_B2 + jg * 4]);
#pragma unroll
            for (int i = 0; i < 64; i++) {
                float4 w = ld4(&sm[E_OFF_W2 + i * 64 + jg * 4]);
                acc.x += h1[i] * w.x;
                acc.y += h1[i] * w.y;
                acc.z += h1[i] * w.z;
                acc.w += h1[i] * w.w;
            }
            h2[jg * 4 + 0] = siluf_(acc.x);
            h2[jg * 4 + 1] = siluf_(acc.y);
            h2[jg * 4 + 2] = siluf_(acc.z);
            h2[jg * 4 + 3] = siluf_(acc.w);
        }

        // scal = h2 @ w3 + b3, written in [region][E][32] layout, 16 cols per group
#pragma unroll 1
        for (int jg = 0; jg < 8; jg++) {
            int col0 = jg * 16;
            float4 a0 = ld4(&sm[E_OFF_B3 + col0]);
            float4 a1 = ld4(&sm[E_OFF_B3 + col0 + 4]);
            float4 a2 = ld4(&sm[E_OFF_B3 + col0 + 8]);
            float4 a3 = ld4(&sm[E_OFF_B3 + col0 + 12]);
#pragma unroll
            for (int k = 0; k < 64; k++) {
                float hk = h2[k];
                const float* wr = &sm[E_OFF_W3 + k * 128 + col0];
                float4 q0 = ld4(wr), q1 = ld4(wr + 4);
                float4 q2 = ld4(wr + 8), q3 = ld4(wr + 12);
                a0.x += hk * q0.x; a0.y += hk * q0.y; a0.z += hk * q0.z; a0.w += hk * q0.w;
                a1.x += hk * q1.x; a1.y += hk * q1.y; a1.z += hk * q1.z; a1.w += hk * q1.w;
                a2.x += hk * q2.x; a2.y += hk * q2.y; a2.z += hk * q2.z; a2.w += hk * q2.w;
                a3.x += hk * q3.x; a3.y += hk * q3.y; a3.z += hk * q3.z; a3.w += hk * q3.w;
            }
            int r = jg >> 1;               // region = col/32
            int moff = (jg & 1) * 16;      // m offset within region
            float* p = g_scal + ((size_t)r * E + e) * 32 + moff;
            st4(p, a0); st4(p + 4, a1); st4(p + 8, a2); st4(p + 12, a3);
        }
    }
}

// ---------------- gather kernel: recompute tensor product + segment mean ----------------
// one warp per node, lane = channel m
__global__ __launch_bounds__(256) void gather_kernel(
    const float* __restrict__ node_scalars,
    const float* __restrict__ node_vectors,
    const float* __restrict__ sh,
    const int* __restrict__ senders,
    int N, int E)
{
    int w = (blockIdx.x * blockDim.x + threadIdx.x) >> 5;
    int lane = threadIdx.x & 31;
    if (w >= N) return;
    int s = g_rowptr[w], t = g_rowptr[w + 1];

    float as0 = 0.f, as1 = 0.f;                         // agg_s[m], agg_s[32+m]
    float v0x = 0.f, v0y = 0.f, v0z = 0.f;              // agg_v channel m
    float v1x = 0.f, v1y = 0.f, v1z = 0.f;              // agg_v channel 32+m

    const size_t r1 = (size_t)1 * E, r2 = (size_t)2 * E, r3 = (size_t)3 * E;

    for (int i = s; i < t; i++) {
        int eid = g_eidx[i];
        size_t base = (size_t)eid * 32 + lane;
        float c0 = g_scal[base];
        float c1 = g_scal[r1 * 32 + base];
        float c2 = g_scal[r2 * 32 + base];
        float c3 = g_scal[r3 * 32 + base];
        float4 shv = ld4(sh + 4 * (size_t)eid);
        int snd = senders[eid];
        float sv = node_scalars[(size_t)snd * 32 + lane];
        const float* vr = node_vectors + (size_t)snd * 96 + 3 * lane;
        float vx = vr[0], vy = vr[1], vz = vr[2];

        float y0 = shv.x, y1x = shv.y, y1y = shv.z, y1z = shv.w;
        float dv = (y1x * vx + y1y * vy + y1z * vz) * 0.5773502691896258f; // /sqrt(3)

        as0 += y0 * sv * c0;
        as1 += dv * c1;
        float g2 = y0 * c2;
        v0x += g2 * vx; v0y += g2 * vy; v0z += g2 * vz;
        float g3 = sv * c3;
        v1x += g3 * y1x; v1y += g3 * y1y; v1z += g3 * y1z;
    }
    float inv = 1.0f / fmaxf((float)(t - s), 1.0f);
    float* out = g_agg + (size_t)w * 256;
    out[lane]      = as0 * inv;
    out[32 + lane] = as1 * inv;
    float* av = out + 64;                 // agg_v: [64 channels][3]
    av[3 * lane + 0]      = v0x * inv;
    av[3 * lane + 1]      = v0y * inv;
    av[3 * lane + 2]      = v0z * inv;
    av[96 + 3 * lane + 0] = v1x * inv;
    av[96 + 3 * lane + 1] = v1y * inv;
    av[96 + 3 * lane + 2] = v1z * inv;
}

// ---------------- node kernel: gated linears ----------------
// smem layout (floats):
//   [0,12288)      W1sT : W1sT[o*64+i] = lin1_w_s[i*192+o]   (192 rows of 64)
//   [12288,16384)  W1vT : W1vT[o*64+m] = lin1_w_v[m*64+o]    (64 rows of 64)
//   [16384,21504)  W2s  : lin2_w_s row-major (160x32)
//   [21504,24576)  W2v  : lin2_w_v row-major (96x32)
#define N_OFF_W1ST 0
#define N_OFF_W1VT 12288
#define N_OFF_W2S  16384
#define N_OFF_W2V  21504
#define NODE_SMEM_FLOATS 24576

__global__ __launch_bounds__(128) void node_kernel(
    const float* __restrict__ node_scalars,
    const float* __restrict__ node_vectors,
    const float* __restrict__ l1s, const float* __restrict__ l1v,
    const float* __restrict__ l2s, const float* __restrict__ l2v,
    float* __restrict__ out,
    int N)
{
    extern __shared__ float sm[];
    for (int i = threadIdx.x; i < 12288; i += blockDim.x) {
        int o = i >> 6, ii = i & 63;
        sm[N_OFF_W1ST + i] = l1s[ii * 192 + o];
    }
    for (int i = threadIdx.x; i < 4096; i += blockDim.x) {
        int o = i >> 6, m = i & 63;
        sm[N_OFF_W1VT + i] = l1v[m * 64 + o];
    }
    for (int i = threadIdx.x; i < 5120; i += blockDim.x) sm[N_OFF_W2S + i] = l2s[i];
    for (int i = threadIdx.x; i < 3072; i += blockDim.x) sm[N_OFF_W2V + i] = l2v[i];
    __syncthreads();

    int n = blockIdx.x * blockDim.x + threadIdx.x;
    if (n >= N) return;

    const float* agg_n = g_agg + (size_t)n * 256;

    // load agg_s into registers
    float as[64];
#pragma unroll
    for (int i4 = 0; i4 < 16; i4++) {
        float4 v = ld4(agg_n + i4 * 4);
        as[i4 * 4 + 0] = v.x; as[i4 * 4 + 1] = v.y;
        as[i4 * 4 + 2] = v.z; as[i4 * 4 + 3] = v.w;
    }

    // ---- scalar path: o_s accumulators ----
    float os[32];
#pragma unroll
    for (int k = 0; k < 32; k++) os[k] = 0.f;

    for (int o = 0; o < 128; o++) {
        const float* wr = &sm[N_OFF_W1ST + o * 64];
        float acc0 = 0.f, acc1 = 0.f, acc2 = 0.f, acc3 = 0.f;
#pragma unroll
        for (int i = 0; i < 64; i += 4) {
            float4 w = ld4(wr + i);
            acc0 += as[i] * w.x;  acc1 += as[i + 1] * w.y;
            acc2 += as[i + 2] * w.z; acc3 += as[i + 3] * w.w;
        }
        float x = (acc0 + acc1 + acc2 + acc3) * 0.125f; // /sqrt(64)
        float a = siluf_(x);
        const float* w2r = &sm[N_OFF_W2S + o * 32];
#pragma unroll
        for (int kg = 0; kg < 8; kg++) {
            float4 w = ld4(w2r + kg * 4);
            os[kg * 4 + 0] += a * w.x; os[kg * 4 + 1] += a * w.y;
            os[kg * 4 + 2] += a * w.z; os[kg * 4 + 3] += a * w.w;
        }
    }
    // node_scalars tail (rows 128..159)
    const float* snode = node_scalars + (size_t)n * 32;
    for (int j = 0; j < 32; j++) {
        float sv = snode[j];
        const float* w2r = &sm[N_OFF_W2S + (128 + j) * 32];
#pragma unroll
        for (int kg = 0; kg < 8; kg++) {
            float4 w = ld4(w2r + kg * 4);
            os[kg * 4 + 0] += sv * w.x; os[kg * 4 + 1] += sv * w.y;
            os[kg * 4 + 2] += sv * w.z; os[kg * 4 + 3] += sv * w.w;
        }
    }
    float* orow = out + (size_t)n * 128;
#pragma unroll
    for (int k = 0; k < 32; k++) orow[k] = os[k] * 0.07905694150420949f; // 1/sqrt(160)

    // ---- gates: sigmoid(x_s[128+o]) -> global scratch ----
    float* gg = g_gates + (size_t)n * 64;
    for (int o = 0; o < 64; o++) {
        const float* wr = &sm[N_OFF_W1ST + (128 + o) * 64];
        float acc0 = 0.f, acc1 = 0.f, acc2 = 0.f, acc3 = 0.f;
#pragma unroll
        for (int i = 0; i < 64; i += 4) {
            float4 w = ld4(wr + i);
            acc0 += as[i] * w.x;  acc1 += as[i + 1] * w.y;
            acc2 += as[i + 2] * w.z; acc3 += as[i + 3] * w.w;
        }
        gg[o] = sigmoidf_((acc0 + acc1 + acc2 + acc3) * 0.125f);
    }

    // ---- vector path, per component ----
    const float* vnode = node_vectors + (size_t)n * 96;
#pragma unroll 1
    for (int c = 0; c < 3; c++) {
        float avc[64];
#pragma unroll
        for (int ch = 0; ch < 64; ch++) avc[ch] = agg_n[64 + ch * 3 + c];
        float ov[32];
#pragma unroll
        for (int k = 0; k < 32; k++) ov[k] = 0.f;

        for (int o = 0; o < 64; o++) {
            const float* wr = &sm[N_OFF_W1VT + o * 64];
            float acc0 = 0.f, acc1 = 0.f, acc2 = 0.f, acc3 = 0.f;
#pragma unroll
            for (int m = 0; m < 64; m += 4) {
                float4 w = ld4(wr + m);
                acc0 += avc[m] * w.x;  acc1 += avc[m + 1] * w.y;
                acc2 += avc[m + 2] * w.z; acc3 += avc[m + 3] * w.w;
            }
            float xv = (acc0 + acc1 + acc2 + acc3) * 0.125f;
            float g = gg[o] * xv;
            const float* w2r = &sm[N_OFF_W2V + o * 32];
#pragma unroll
            for (int kg = 0; kg < 8; kg++) {
                float4 w = ld4(w2r + kg * 4);
                ov[kg * 4 + 0] += g * w.x; ov[kg * 4 + 1] += g * w.y;
                ov[kg * 4 + 2] += g * w.z; ov[kg * 4 + 3] += g * w.w;
            }
        }
        // node_vectors tail (rows 64..95)
        for (int j = 0; j < 32; j++) {
            float vv = vnode[3 * j + c];
            const float* w2r = &sm[N_OFF_W2V + (64 + j) * 32];
#pragma unroll
            for (int kg = 0; kg < 8; kg++) {
                float4 w = ld4(w2r + kg * 4);
                ov[kg * 4 + 0] += vv * w.x; ov[kg * 4 + 1] += vv * w.y;
                ov[kg * 4 + 2] += vv * w.z; ov[kg * 4 + 3] += vv * w.w;
            }
        }
#pragma unroll
        for (int k = 0; k < 32; k++)
            orow[32 + k * 3 + c] = ov[k] * 0.10206207261596577f; // 1/sqrt(96)
    }
}

// ---------------- launch ----------------
extern "C" void kernel_launch(void* const* d_in, const int* in_sizes, int n_in,
                              void* d_out, int out_size)
{
    const float* node_scalars = (const float*)d_in[0];
    const float* node_vectors = (const float*)d_in[1];
    const float* sh           = (const float*)d_in[2];
    const float* norm         = (const float*)d_in[3];
    const float* w1           = (const float*)d_in[4];
    const float* b1           = (const float*)d_in[5];
    const float* w2           = (const float*)d_in[6];
    const float* b2           = (const float*)d_in[7];
    const float* w3           = (const float*)d_in[8];
    const float* b3           = (const float*)d_in[9];
    const float* l1s          = (const float*)d_in[10];
    const float* l1v          = (const float*)d_in[11];
    const float* l2s          = (const float*)d_in[12];
    const float* l2v          = (const float*)d_in[13];
    const int*   senders      = (const int*)d_in[14];
    const int*   receivers    = (const int*)d_in[15];
    float* out = (float*)d_out;

    int N = in_sizes[0] / MUL;   // node_scalars (N, 32)
    int E = in_sizes[2] / 4;     // sh (E, 4)
    if (N > NMAX) N = NMAX;
    if (E > EMAX) E = EMAX;

    cudaFuncSetAttribute(edge_kernel, cudaFuncAttributeMaxDynamicSharedMemorySize,
                         EDGE_SMEM_FLOATS * 4);
    cudaFuncSetAttribute(node_kernel, cudaFuncAttributeMaxDynamicSharedMemorySize,
                         NODE_SMEM_FLOATS * 4);

    zero_deg_kernel<<<(N + 255) / 256, 256>>>(N);
    count_deg_kernel<<<(E + 255) / 256, 256>>>(receivers, E);
    scan_kernel<<<1, 1024>>>(N);
    scatter_kernel<<<(E + 255) / 256, 256>>>(receivers, E);

    edge_kernel<<<(E + 255) / 256, 256, EDGE_SMEM_FLOATS * 4>>>(
        norm, w1, b1, w2, b2, w3, b3, E);

    gather_kernel<<<(N + 7) / 8, 256>>>(
        node_scalars, node_vectors, sh, senders, N, E);

    node_kernel<<<(N + 127) / 128, 128, NODE_SMEM_FLOATS * 4>>>(
        node_scalars, node_vectors, l1s, l1v, l2s, l2v, out, N);
}

// round 14
// speedup vs baseline: 2.1923x; 2.1923x over previous
#include <cuda_runtime.h>
#include <cuda_bf16.h>
#include <math.h>

// Problem constants (fixed shapes for this dataset)
#define MUL  32
#define HID  64
#define NMAX 50000
#define EMAX 400000
#define LUTN 8192            // intervals; 8193 knot rows

// ---------------- static device scratch (no allocations allowed) ----------------
__device__ float g_lut[(size_t)(LUTN + 1) * 128];   // scal(x) at knots, row-major [knot][128]
__device__ float g_agg[(size_t)NMAX * 256];         // per node: agg_s[64] + agg_v[64*3]
__device__ float g_gates[(size_t)NMAX * 64];        // sigmoid gates scratch
__device__ int   g_deg[NMAX];
__device__ int   g_rowptr[NMAX + 1];
__device__ int   g_cursor[NMAX];
__device__ int   g_eidx[EMAX];
__device__ int   g_blocksums[64];
__device__ int   g_blockoff[64];

__device__ __forceinline__ float4 ld4(const float* p) {
    return *reinterpret_cast<const float4*>(p);
}
__device__ __forceinline__ float sigmoidf_(float x) {
    return 1.0f / (1.0f + __expf(-x));
}
__device__ __forceinline__ float siluf_(float x) {
    return x * sigmoidf_(x);
}

// ---------------- CSR build ----------------
__global__ void count_deg_kernel(const int* __restrict__ recv, int e) {
    int i = blockIdx.x * blockDim.x + threadIdx.x;
    if (i < e) atomicAdd(&g_deg[recv[i]], 1);
}

// phase 1: per-block exclusive scan of degrees (1024/block), block sums out
__global__ __launch_bounds__(1024) void scan1_kernel(int n) {
    __shared__ int warp_sums[32];
    int t = threadIdx.x;
    int i = blockIdx.x * 1024 + t;
    int lane = t & 31, wid = t >> 5;
    int v = (i < n) ? g_deg[i] : 0;
    int x = v;
#pragma unroll
    for (int off = 1; off < 32; off <<= 1) {
        int y = __shfl_up_sync(0xffffffffu, x, off);
        if (lane >= off) x += y;
    }
    if (lane == 31) warp_sums[wid] = x;
    __syncthreads();
    if (wid == 0) {
        int s = warp_sums[lane];
#pragma unroll
        for (int off = 1; off < 32; off <<= 1) {
            int y = __shfl_up_sync(0xffffffffu, s, off);
            if (lane >= off) s += y;
        }
        warp_sums[lane] = s;
    }
    __syncthreads();
    int excl = x - v + (wid > 0 ? warp_sums[wid - 1] : 0);
    if (i < n) g_rowptr[i] = excl;
    if (t == 1023) g_blocksums[blockIdx.x] = excl + v;
}

// phase 2: serial exclusive scan of block sums (<=64 of them)
__global__ void scan2_kernel(int nb, int n) {
    if (threadIdx.x == 0) {
        int run = 0;
        for (int b = 0; b < nb; b++) {
            g_blockoff[b] = run;
            run += g_blocksums[b];
        }
        g_rowptr[n] = run;
    }
}

// phase 3: add block offsets, init cursor
__global__ __launch_bounds__(1024) void scan3_kernel(int n) {
    int i = blockIdx.x * 1024 + threadIdx.x;
    if (i < n) {
        int r = g_rowptr[i] + g_blockoff[blockIdx.x];
        g_rowptr[i] = r;
        g_cursor[i] = r;
    }
}

__global__ void scatter_kernel(const int* __restrict__ recv, int e) {
    int i = blockIdx.x * blockDim.x + threadIdx.x;
    if (i < e) {
        int pos = atomicAdd(&g_cursor[recv[i]], 1);
        g_eidx[pos] = i;
    }
}

// ---------------- LUT build: evaluate the 3-layer MLP at 8193 knots ----------------
// dynamic smem layout (floats): w1[64] b1[64] b2[64] b3[128] w2[64x64] w3[64x128]
#define E_OFF_W1  0
#define E_OFF_B1  64
#define E_OFF_B2  128
#define E_OFF_B3  192
#define E_OFF_W2  320
#define E_OFF_W3  4416
#define LUT_SMEM_FLOATS 12608

__global__ __launch_bounds__(256) void lut_kernel(
    const float* __restrict__ w1, const float* __restrict__ b1,
    const float* __restrict__ w2, const float* __restrict__ b2,
    const float* __restrict__ w3, const float* __restrict__ b3)
{
    extern __shared__ float sm[];
    for (int i = threadIdx.x; i < 64; i += blockDim.x) {
        sm[E_OFF_W1 + i] = w1[i];
        sm[E_OFF_B1 + i] = b1[i];
        sm[E_OFF_B2 + i] = b2[i];
    }
    for (int i = threadIdx.x; i < 128; i += blockDim.x) sm[E_OFF_B3 + i] = b3[i];
    for (int i = threadIdx.x; i < 4096; i += blockDim.x) sm[E_OFF_W2 + i] = w2[i];
    for (int i = threadIdx.x; i < 8192; i += blockDim.x) sm[E_OFF_W3 + i] = w3[i];
    __syncthreads();

    int k = blockIdx.x * blockDim.x + threadIdx.x;
    if (k > LUTN) return;
    float nv = (float)k * (1.0f / (float)LUTN);

    float h1[64];
#pragma unroll
    for (int j = 0; j < 64; j++)
        h1[j] = siluf_(nv * sm[E_OFF_W1 + j] + sm[E_OFF_B1 + j]);

    float h2[64];
#pragma unroll
    for (int jg = 0; jg < 16; jg++) {
        float4 acc = ld4(&sm[E_OFF_B2 + jg * 4]);
#pragma unroll
        for (int i = 0; i < 64; i++) {
            float4 w = ld4(&sm[E_OFF_W2 + i * 64 + jg * 4]);
            acc.x += h1[i] * w.x;
            acc.y += h1[i] * w.y;
            acc.z += h1[i] * w.z;
            acc.w += h1[i] * w.w;
        }
        h2[jg * 4 + 0] = siluf_(acc.x);
        h2[jg * 4 + 1] = siluf_(acc.y);
        h2[jg * 4 + 2] = siluf_(acc.z);
        h2[jg * 4 + 3] = siluf_(acc.w);
    }

    float* row = g_lut + (size_t)k * 128;
#pragma unroll 1
    for (int jg = 0; jg < 8; jg++) {
        int col0 = jg * 16;
        float4 a0 = ld4(&sm[E_OFF_B3 + col0]);
        float4 a1 = ld4(&sm[E_OFF_B3 + col0 + 4]);
        float4 a2 = ld4(&sm[E_OFF_B3 + col0 + 8]);
        float4 a3 = ld4(&sm[E_OFF_B3 + col0 + 12]);
#pragma unroll
        for (int kk = 0; kk < 64; kk++) {
            float hk = h2[kk];
            const float* wr = &sm[E_OFF_W3 + kk * 128 + col0];
            float4 q0 = ld4(wr), q1 = ld4(wr + 4);
            float4 q2 = ld4(wr + 8), q3 = ld4(wr + 12);
            a0.x += hk * q0.x; a0.y += hk * q0.y; a0.z += hk * q0.z; a0.w += hk * q0.w;
            a1.x += hk * q1.x; a1.y += hk * q1.y; a1.z += hk * q1.z; a1.w += hk * q1.w;
            a2.x += hk * q2.x; a2.y += hk * q2.y; a2.z += hk * q2.z; a2.w += hk * q2.w;
            a3.x += hk * q3.x; a3.y += hk * q3.y; a3.z += hk * q3.z; a3.w += hk * q3.w;
        }
        *reinterpret_cast<float4*>(row + col0)      = a0;
        *reinterpret_cast<float4*>(row + col0 + 4)  = a1;
        *reinterpret_cast<float4*>(row + col0 + 8)  = a2;
        *reinterpret_cast<float4*>(row + col0 + 12) = a3;
    }
}

// ---------------- gather kernel: LUT-lerp scal + tensor product + segment mean ----------------
// one warp per node, lane = channel m
__global__ __launch_bounds__(256) void gather_kernel(
    const float* __restrict__ node_scalars,
    const float* __restrict__ node_vectors,
    const float* __restrict__ sh,
    const float* __restrict__ norm,
    const int* __restrict__ senders,
    int N)
{
    int w = (blockIdx.x * blockDim.x + threadIdx.x) >> 5;
    int lane = threadIdx.x & 31;
    if (w >= N) return;
    int s = g_rowptr[w], t = g_rowptr[w + 1];

    float as0 = 0.f, as1 = 0.f;                         // agg_s[m], agg_s[32+m]
    float v0x = 0.f, v0y = 0.f, v0z = 0.f;              // agg_v channel m
    float v1x = 0.f, v1y = 0.f, v1z = 0.f;              // agg_v channel 32+m

    for (int i = s; i < t; i++) {
        int eid = g_eidx[i];
        float x = norm[eid];
        float4 shv = ld4(sh + 4 * (size_t)eid);
        int snd = senders[eid];

        // LUT lerp for scal columns {m, 32+m, 64+m, 96+m}
        float xf = x * (float)LUTN;
        int k = (int)xf;
        k = min(max(k, 0), LUTN - 1);
        float tt = xf - (float)k;
        const float* L = g_lut + (size_t)k * 128;
        float l00 = L[lane],        l01 = L[128 + lane];
        float l10 = L[32 + lane],   l11 = L[160 + lane];
        float l20 = L[64 + lane],   l21 = L[192 + lane];
        float l30 = L[96 + lane],   l31 = L[224 + lane];
        float c0 = l00 + tt * (l01 - l00);
        float c1 = l10 + tt * (l11 - l10);
        float c2 = l20 + tt * (l21 - l20);
        float c3 = l30 + tt * (l31 - l30);

        float sv = node_scalars[(size_t)snd * 32 + lane];
        const float* vr = node_vectors + (size_t)snd * 96 + 3 * lane;
        float vx = vr[0], vy = vr[1], vz = vr[2];

        float y0 = shv.x, y1x = shv.y, y1y = shv.z, y1z = shv.w;
        float dv = (y1x * vx + y1y * vy + y1z * vz) * 0.5773502691896258f; // /sqrt(3)

        as0 += y0 * sv * c0;
        as1 += dv * c1;
        float g2 = y0 * c2;
        v0x += g2 * vx; v0y += g2 * vy; v0z += g2 * vz;
        float g3 = sv * c3;
        v1x += g3 * y1x; v1y += g3 * y1y; v1z += g3 * y1z;
    }
    float inv = 1.0f / fmaxf((float)(t - s), 1.0f);
    float* out = g_agg + (size_t)w * 256;
    out[lane]      = as0 * inv;
    out[32 + lane] = as1 * inv;
    float* av = out + 64;                 // agg_v: [64 channels][3]
    av[3 * lane + 0]      = v0x * inv;
    av[3 * lane + 1]      = v0y * inv;
    av[3 * lane + 2]      = v0z * inv;
    av[96 + 3 * lane + 0] = v1x * inv;
    av[96 + 3 * lane + 1] = v1y * inv;
    av[96 + 3 * lane + 2] = v1z * inv;
}

// ---------------- node kernel: gated linears ----------------
// smem layout (floats):
//   [0,12288)      W1sT : W1sT[o*64+i] = lin1_w_s[i*192+o]   (192 rows of 64)
//   [12288,16384)  W1vT : W1vT[o*64+m] = lin1_w_v[m*64+o]    (64 rows of 64)
//   [16384,21504)  W2s  : lin2_w_s row-major (160x32)
//   [21504,24576)  W2v  : lin2_w_v row-major (96x32)
#define N_OFF_W1ST 0
#define N_OFF_W1VT 12288
#define N_OFF_W2S  16384
#define N_OFF_W2V  21504
#define NODE_SMEM_FLOATS 24576

__global__ __launch_bounds__(128) void node_kernel(
    const float* __restrict__ node_scalars,
    const float* __restrict__ node_vectors,
    const float* __restrict__ l1s, const float* __restrict__ l1v,
    const float* __restrict__ l2s, const float* __restrict__ l2v,
    float* __restrict__ out,
    int N)
{
    extern __shared__ float sm[];
    for (int i = threadIdx.x; i < 12288; i += blockDim.x) {
        int o = i >> 6, ii = i & 63;
        sm[N_OFF_W1ST + i] = l1s[ii * 192 + o];
    }
    for (int i = threadIdx.x; i < 4096; i += blockDim.x) {
        int o = i >> 6, m = i & 63;
        sm[N_OFF_W1VT + i] = l1v[m * 64 + o];
    }
    for (int i = threadIdx.x; i < 5120; i += blockDim.x) sm[N_OFF_W2S + i] = l2s[i];
    for (int i = threadIdx.x; i < 3072; i += blockDim.x) sm[N_OFF_W2V + i] = l2v[i];
    __syncthreads();

    int n = blockIdx.x * blockDim.x + threadIdx.x;
    if (n >= N) return;

    const float* agg_n = g_agg + (size_t)n * 256;

    float as[64];
#pragma unroll
    for (int i4 = 0; i4 < 16; i4++) {
        float4 v = ld4(agg_n + i4 * 4);
        as[i4 * 4 + 0] = v.x; as[i4 * 4 + 1] = v.y;
        as[i4 * 4 + 2] = v.z; as[i4 * 4 + 3] = v.w;
    }

    // ---- scalar path ----
    float os[32];
#pragma unroll
    for (int k = 0; k < 32; k++) os[k] = 0.f;

    for (int o = 0; o < 128; o++) {
        const float* wr = &sm[N_OFF_W1ST + o * 64];
        float acc0 = 0.f, acc1 = 0.f, acc2 = 0.f, acc3 = 0.f;
#pragma unroll
        for (int i = 0; i < 64; i += 4) {
            float4 w = ld4(wr + i);
            acc0 += as[i] * w.x;  acc1 += as[i + 1] * w.y;
            acc2 += as[i + 2] * w.z; acc3 += as[i + 3] * w.w;
        }
        float x = (acc0 + acc1 + acc2 + acc3) * 0.125f; // /sqrt(64)
        float a = siluf_(x);
        const float* w2r = &sm[N_OFF_W2S + o * 32];
#pragma unroll
        for (int kg = 0; kg < 8; kg++) {
            float4 w = ld4(w2r + kg * 4);
            os[kg * 4 + 0] += a * w.x; os[kg * 4 + 1] += a * w.y;
            os[kg * 4 + 2] += a * w.z; os[kg * 4 + 3] += a * w.w;
        }
    }
    const float* snode = node_scalars + (size_t)n * 32;
    for (int j = 0; j < 32; j++) {
        float sv = snode[j];
        const float* w2r = &sm[N_OFF_W2S + (128 + j) * 32];
#pragma unroll
        for (int kg = 0; kg < 8; kg++) {
            float4 w = ld4(w2r + kg * 4);
            os[kg * 4 + 0] += sv * w.x; os[kg * 4 + 1] += sv * w.y;
            os[kg * 4 + 2] += sv * w.z; os[kg * 4 + 3] += sv * w.w;
        }
    }
    float* orow = out + (size_t)n * 128;
#pragma unroll
    for (int k = 0; k < 32; k++) orow[k] = os[k] * 0.07905694150420949f; // 1/sqrt(160)

    // ---- gates -> global scratch ----
    float* gg = g_gates + (size_t)n * 64;
    for (int o = 0; o < 64; o++) {
        const float* wr = &sm[N_OFF_W1ST + (128 + o) * 64];
        float acc0 = 0.f, acc1 = 0.f, acc2 = 0.f, acc3 = 0.f;
#pragma unroll
        for (int i = 0; i < 64; i += 4) {
            float4 w = ld4(wr + i);
            acc0 += as[i] * w.x;  acc1 += as[i + 1] * w.y;
            acc2 += as[i + 2] * w.z; acc3 += as[i + 3] * w.w;
        }
        gg[o] = sigmoidf_((acc0 + acc1 + acc2 + acc3) * 0.125f);
    }

    // ---- vector path, per component ----
    const float* vnode = node_vectors + (size_t)n * 96;
#pragma unroll 1
    for (int c = 0; c < 3; c++) {
        float avc[64];
#pragma unroll
        for (int ch = 0; ch < 64; ch++) avc[ch] = agg_n[64 + ch * 3 + c];
        float ov[32];
#pragma unroll
        for (int k = 0; k < 32; k++) ov[k] = 0.f;

        for (int o = 0; o < 64; o++) {
            const float* wr = &sm[N_OFF_W1VT + o * 64];
            float acc0 = 0.f, acc1 = 0.f, acc2 = 0.f, acc3 = 0.f;
#pragma unroll
            for (int m = 0; m < 64; m += 4) {
                float4 w = ld4(wr + m);
                acc0 += avc[m] * w.x;  acc1 += avc[m + 1] * w.y;
                acc2 += avc[m + 2] * w.z; acc3 += avc[m + 3] * w.w;
            }
            float xv = (acc0 + acc1 + acc2 + acc3) * 0.125f;
            float g = gg[o] * xv;
            const float* w2r = &sm[N_OFF_W2V + o * 32];
#pragma unroll
            for (int kg = 0; kg < 8; kg++) {
                float4 w = ld4(w2r + kg * 4);
                ov[kg * 4 + 0] += g * w.x; ov[kg * 4 + 1] += g * w.y;
                ov[kg * 4 + 2] += g * w.z; ov[kg * 4 + 3] += g * w.w;
            }
        }
        for (int j = 0; j < 32; j++) {
            float vv = vnode[3 * j + c];
            const float* w2r = &sm[N_OFF_W2V + (64 + j) * 32];
#pragma unroll
            for (int kg = 0; kg < 8; kg++) {
                float4 w = ld4(w2r + kg * 4);
                ov[kg * 4 + 0] += vv * w.x; ov[kg * 4 + 1] += vv * w.y;
                ov[kg * 4 + 2] += vv * w.z; ov[kg * 4 + 3] += vv * w.w;
            }
        }
#pragma unroll
        for (int k = 0; k < 32; k++)
            orow[32 + k * 3 + c] = ov[k] * 0.10206207261596577f; // 1/sqrt(96)
    }
}

// ---------------- launch ----------------
extern "C" void kernel_launch(void* const* d_in, const int* in_sizes, int n_in,
                              void* d_out, int out_size)
{
    const float* node_scalars = (const float*)d_in[0];
    const float* node_vectors = (const float*)d_in[1];
    const float* sh           = (const float*)d_in[2];
    const float* norm         = (const float*)d_in[3];
    const float* w1           = (const float*)d_in[4];
    const float* b1           = (const float*)d_in[5];
    const float* w2           = (const float*)d_in[6];
    const float* b2           = (const float*)d_in[7];
    const float* w3           = (const float*)d_in[8];
    const float* b3           = (const float*)d_in[9];
    const float* l1s          = (const float*)d_in[10];
    const float* l1v          = (const float*)d_in[11];
    const float* l2s          = (const float*)d_in[12];
    const float* l2v          = (const float*)d_in[13];
    const int*   senders      = (const int*)d_in[14];
    const int*   receivers    = (const int*)d_in[15];
    float* out = (float*)d_out;

    int N = in_sizes[0] / MUL;   // node_scalars (N, 32)
    int E = in_sizes[2] / 4;     // sh (E, 4)
    if (N > NMAX) N = NMAX;
    if (E > EMAX) E = EMAX;

    cudaFuncSetAttribute(lut_kernel, cudaFuncAttributeMaxDynamicSharedMemorySize,
                         LUT_SMEM_FLOATS * 4);
    cudaFuncSetAttribute(node_kernel, cudaFuncAttributeMaxDynamicSharedMemorySize,
                         NODE_SMEM_FLOATS * 4);

    int nb = (N + 1023) / 1024;

    // LUT build first (independent of CSR) so it overlaps the CSR phase
    lut_kernel<<<(LUTN + 1 + 255) / 256, 256, LUT_SMEM_FLOATS * 4>>>(
        w1, b1, w2, b2, w3, b3);

    void* degptr = nullptr;
    cudaGetSymbolAddress(&degptr, g_deg);
    cudaMemsetAsync(degptr, 0, NMAX * sizeof(int));

    count_deg_kernel<<<(E + 255) / 256, 256>>>(receivers, E);
    scan1_kernel<<<nb, 1024>>>(N);
    scan2_kernel<<<1, 32>>>(nb, N);
    scan3_kernel<<<nb, 1024>>>(N);
    scatter_kernel<<<(E + 255) / 256, 256>>>(receivers, E);

    gather_kernel<<<(N + 7) / 8, 256>>>(
        node_scalars, node_vectors, sh, norm, senders, N);

    node_kernel<<<(N + 127) / 128, 128, NODE_SMEM_FLOATS * 4>>>(
        node_scalars, node_vectors, l1s, l1v, l2s, l2v, out, N);
}

// round 15
// speedup vs baseline: 2.8021x; 1.2782x over previous
#include <cuda_runtime.h>
#include <cuda_bf16.h>
#include <math.h>

// Problem constants (fixed shapes for this dataset)
#define MUL  32
#define HID  64
#define NMAX 50000
#define EMAX 400000
#define LUTN 8192            // intervals; 8193 knot rows

// ---------------- static device scratch (no allocations allowed) ----------------
__device__ float g_lut[(size_t)(LUTN + 1) * 128];   // scal(x) at knots, row-major [knot][128]
__device__ float g_agg[(size_t)NMAX * 256];         // per node: agg_s[64] + agg_v[64*3]
__device__ float g_gates[(size_t)NMAX * 64];        // sigmoid gates scratch
__device__ int   g_deg[NMAX];
__device__ int   g_rowptr[NMAX + 1];
__device__ int   g_cursor[NMAX];
__device__ int   g_eidx[EMAX];
__device__ int   g_blocksums[64];
__device__ int   g_blockoff[64];

__device__ __forceinline__ float4 ld4(const float* p) {
    return *reinterpret_cast<const float4*>(p);
}
__device__ __forceinline__ float sigmoidf_(float x) {
    return 1.0f / (1.0f + __expf(-x));
}
__device__ __forceinline__ float siluf_(float x) {
    return x * sigmoidf_(x);
}

// ---------------- CSR build ----------------
__global__ void count_deg_kernel(const int* __restrict__ recv, int e) {
    int i = blockIdx.x * blockDim.x + threadIdx.x;
    if (i < e) atomicAdd(&g_deg[recv[i]], 1);
}

// phase 1: per-block exclusive scan of degrees (1024/block), block sums out
__global__ __launch_bounds__(1024) void scan1_kernel(int n) {
    __shared__ int warp_sums[32];
    int t = threadIdx.x;
    int i = blockIdx.x * 1024 + t;
    int lane = t & 31, wid = t >> 5;
    int v = (i < n) ? g_deg[i] : 0;
    int x = v;
#pragma unroll
    for (int off = 1; off < 32; off <<= 1) {
        int y = __shfl_up_sync(0xffffffffu, x, off);
        if (lane >= off) x += y;
    }
    if (lane == 31) warp_sums[wid] = x;
    __syncthreads();
    if (wid == 0) {
        int s = warp_sums[lane];
#pragma unroll
        for (int off = 1; off < 32; off <<= 1) {
            int y = __shfl_up_sync(0xffffffffu, s, off);
            if (lane >= off) s += y;
        }
        warp_sums[lane] = s;
    }
    __syncthreads();
    int excl = x - v + (wid > 0 ? warp_sums[wid - 1] : 0);
    if (i < n) g_rowptr[i] = excl;
    if (t == 1023) g_blocksums[blockIdx.x] = excl + v;
}

// phase 2: serial exclusive scan of block sums (<=64 of them)
__global__ void scan2_kernel(int nb, int n) {
    if (threadIdx.x == 0) {
        int run = 0;
        for (int b = 0; b < nb; b++) {
            g_blockoff[b] = run;
            run += g_blocksums[b];
        }
        g_rowptr[n] = run;
    }
}

// phase 3: add block offsets, init cursor
__global__ __launch_bounds__(1024) void scan3_kernel(int n) {
    int i = blockIdx.x * 1024 + threadIdx.x;
    if (i < n) {
        int r = g_rowptr[i] + g_blockoff[blockIdx.x];
        g_rowptr[i] = r;
        g_cursor[i] = r;
    }
}

__global__ void scatter_kernel(const int* __restrict__ recv, int e) {
    int i = blockIdx.x * blockDim.x + threadIdx.x;
    if (i < e) {
        int pos = atomicAdd(&g_cursor[recv[i]], 1);
        g_eidx[pos] = i;
    }
}

// ---------------- LUT build: evaluate the 3-layer MLP at 8193 knots ----------------
// dynamic smem layout (floats): w1[64] b1[64] b2[64] b3[128] w2[64x64] w3[64x128]
#define E_OFF_W1  0
#define E_OFF_B1  64
#define E_OFF_B2  128
#define E_OFF_B3  192
#define E_OFF_W2  320
#define E_OFF_W3  4416
#define LUT_SMEM_FLOATS 12608

__global__ __launch_bounds__(256) void lut_kernel(
    const float* __restrict__ w1, const float* __restrict__ b1,
    const float* __restrict__ w2, const float* __restrict__ b2,
    const float* __restrict__ w3, const float* __restrict__ b3)
{
    extern __shared__ float sm[];
    for (int i = threadIdx.x; i < 64; i += blockDim.x) {
        sm[E_OFF_W1 + i] = w1[i];
        sm[E_OFF_B1 + i] = b1[i];
        sm[E_OFF_B2 + i] = b2[i];
    }
    for (int i = threadIdx.x; i < 128; i += blockDim.x) sm[E_OFF_B3 + i] = b3[i];
    for (int i = threadIdx.x; i < 4096; i += blockDim.x) sm[E_OFF_W2 + i] = w2[i];
    for (int i = threadIdx.x; i < 8192; i += blockDim.x) sm[E_OFF_W3 + i] = w3[i];
    __syncthreads();

    int k = blockIdx.x * blockDim.x + threadIdx.x;
    if (k > LUTN) return;
    float nv = (float)k * (1.0f / (float)LUTN);

    float h1[64];
#pragma unroll
    for (int j = 0; j < 64; j++)
        h1[j] = siluf_(nv * sm[E_OFF_W1 + j] + sm[E_OFF_B1 + j]);

    float h2[64];
#pragma unroll
    for (int jg = 0; jg < 16; jg++) {
        float4 acc = ld4(&sm[E_OFF_B2 + jg * 4]);
#pragma unroll
        for (int i = 0; i < 64; i++) {
            float4 w = ld4(&sm[E_OFF_W2 + i * 64 + jg * 4]);
            acc.x += h1[i] * w.x;
            acc.y += h1[i] * w.y;
            acc.z += h1[i] * w.z;
            acc.w += h1[i] * w.w;
        }
        h2[jg * 4 + 0] = siluf_(acc.x);
        h2[jg * 4 + 1] = siluf_(acc.y);
        h2[jg * 4 + 2] = siluf_(acc.z);
        h2[jg * 4 + 3] = siluf_(acc.w);
    }

    float* row = g_lut + (size_t)k * 128;
#pragma unroll 1
    for (int jg = 0; jg < 8; jg++) {
        int col0 = jg * 16;
        float4 a0 = ld4(&sm[E_OFF_B3 + col0]);
        float4 a1 = ld4(&sm[E_OFF_B3 + col0 + 4]);
        float4 a2 = ld4(&sm[E_OFF_B3 + col0 + 8]);
        float4 a3 = ld4(&sm[E_OFF_B3 + col0 + 12]);
#pragma unroll
        for (int kk = 0; kk < 64; kk++) {
            float hk = h2[kk];
            const float* wr = &sm[E_OFF_W3 + kk * 128 + col0];
            float4 q0 = ld4(wr), q1 = ld4(wr + 4);
            float4 q2 = ld4(wr + 8), q3 = ld4(wr + 12);
            a0.x += hk * q0.x; a0.y += hk * q0.y; a0.z += hk * q0.z; a0.w += hk * q0.w;
            a1.x += hk * q1.x; a1.y += hk * q1.y; a1.z += hk * q1.z; a1.w += hk * q1.w;
            a2.x += hk * q2.x; a2.y += hk * q2.y; a2.z += hk * q2.z; a2.w += hk * q2.w;
            a3.x += hk * q3.x; a3.y += hk * q3.y; a3.z += hk * q3.z; a3.w += hk * q3.w;
        }
        *reinterpret_cast<float4*>(row + col0)      = a0;
        *reinterpret_cast<float4*>(row + col0 + 4)  = a1;
        *reinterpret_cast<float4*>(row + col0 + 8)  = a2;
        *reinterpret_cast<float4*>(row + col0 + 12) = a3;
    }
}

// ---------------- gather kernel: LUT-lerp scal + tensor product + segment mean ----------------
// one warp per node, lane = channel m  (UNCHANGED from R14 passing version)
__global__ __launch_bounds__(256) void gather_kernel(
    const float* __restrict__ node_scalars,
    const float* __restrict__ node_vectors,
    const float* __restrict__ sh,
    const float* __restrict__ norm,
    const int* __restrict__ senders,
    int N)
{
    int w = (blockIdx.x * blockDim.x + threadIdx.x) >> 5;
    int lane = threadIdx.x & 31;
    if (w >= N) return;
    int s = g_rowptr[w], t = g_rowptr[w + 1];

    float as0 = 0.f, as1 = 0.f;                         // agg_s[m], agg_s[32+m]
    float v0x = 0.f, v0y = 0.f, v0z = 0.f;              // agg_v channel m
    float v1x = 0.f, v1y = 0.f, v1z = 0.f;              // agg_v channel 32+m

    for (int i = s; i < t; i++) {
        int eid = g_eidx[i];
        float x = norm[eid];
        float4 shv = ld4(sh + 4 * (size_t)eid);
        int snd = senders[eid];

        // LUT lerp for scal columns {m, 32+m, 64+m, 96+m}
        float xf = x * (float)LUTN;
        int k = (int)xf;
        k = min(max(k, 0), LUTN - 1);
        float tt = xf - (float)k;
        const float* L = g_lut + (size_t)k * 128;
        float l00 = L[lane],        l01 = L[128 + lane];
        float l10 = L[32 + lane],   l11 = L[160 + lane];
        float l20 = L[64 + lane],   l21 = L[192 + lane];
        float l30 = L[96 + lane],   l31 = L[224 + lane];
        float c0 = l00 + tt * (l01 - l00);
        float c1 = l10 + tt * (l11 - l10);
        float c2 = l20 + tt * (l21 - l20);
        float c3 = l30 + tt * (l31 - l30);

        float sv = node_scalars[(size_t)snd * 32 + lane];
        const float* vr = node_vectors + (size_t)snd * 96 + 3 * lane;
        float vx = vr[0], vy = vr[1], vz = vr[2];

        float y0 = shv.x, y1x = shv.y, y1y = shv.z, y1z = shv.w;
        float dv = (y1x * vx + y1y * vy + y1z * vz) * 0.5773502691896258f; // /sqrt(3)

        as0 += y0 * sv * c0;
        as1 += dv * c1;
        float g2 = y0 * c2;
        v0x += g2 * vx; v0y += g2 * vy; v0z += g2 * vz;
        float g3 = sv * c3;
        v1x += g3 * y1x; v1y += g3 * y1y; v1z += g3 * y1z;
    }
    float inv = 1.0f / fmaxf((float)(t - s), 1.0f);
    float* out = g_agg + (size_t)w * 256;
    out[lane]      = as0 * inv;
    out[32 + lane] = as1 * inv;
    float* av = out + 64;                 // agg_v: [64 channels][3]
    av[3 * lane + 0]      = v0x * inv;
    av[3 * lane + 1]      = v0y * inv;
    av[3 * lane + 2]      = v0z * inv;
    av[96 + 3 * lane + 0] = v1x * inv;
    av[96 + 3 * lane + 1] = v1y * inv;
    av[96 + 3 * lane + 2] = v1z * inv;
}

// ---------------- node kernel K1: scalar path + gates ----------------
// smem layout (floats):
//   [0,12288)      W1sT : W1sT[o*64+i] = lin1_w_s[i*192+o]   (192 rows of 64)
//   [12288,17408)  W2s  : lin2_w_s row-major (160x32)
#define K1_OFF_W1ST 0
#define K1_OFF_W2S  12288
#define K1_SMEM_FLOATS 17408

__global__ __launch_bounds__(128) void node_scalar_kernel(
    const float* __restrict__ node_scalars,
    const float* __restrict__ l1s, const float* __restrict__ l2s,
    float* __restrict__ out,
    int N)
{
    extern __shared__ float sm[];
    for (int i = threadIdx.x; i < 12288; i += blockDim.x) {
        int o = i >> 6, ii = i & 63;
        sm[K1_OFF_W1ST + i] = l1s[ii * 192 + o];
    }
    for (int i = threadIdx.x; i < 5120; i += blockDim.x) sm[K1_OFF_W2S + i] = l2s[i];
    __syncthreads();

    int n = blockIdx.x * blockDim.x + threadIdx.x;
    if (n >= N) return;

    const float* agg_n = g_agg + (size_t)n * 256;

    float as[64];
#pragma unroll
    for (int i4 = 0; i4 < 16; i4++) {
        float4 v = ld4(agg_n + i4 * 4);
        as[i4 * 4 + 0] = v.x; as[i4 * 4 + 1] = v.y;
        as[i4 * 4 + 2] = v.z; as[i4 * 4 + 3] = v.w;
    }

    float os[32];
#pragma unroll
    for (int k = 0; k < 32; k++) os[k] = 0.f;

    for (int o = 0; o < 128; o++) {
        const float* wr = &sm[K1_OFF_W1ST + o * 64];
        float acc0 = 0.f, acc1 = 0.f, acc2 = 0.f, acc3 = 0.f;
#pragma unroll
        for (int i = 0; i < 64; i += 4) {
            float4 w = ld4(wr + i);
            acc0 += as[i] * w.x;  acc1 += as[i + 1] * w.y;
            acc2 += as[i + 2] * w.z; acc3 += as[i + 3] * w.w;
        }
        float x = (acc0 + acc1 + acc2 + acc3) * 0.125f; // /sqrt(64)
        float a = siluf_(x);
        const float* w2r = &sm[K1_OFF_W2S + o * 32];
#pragma unroll
        for (int kg = 0; kg < 8; kg++) {
            float4 w = ld4(w2r + kg * 4);
            os[kg * 4 + 0] += a * w.x; os[kg * 4 + 1] += a * w.y;
            os[kg * 4 + 2] += a * w.z; os[kg * 4 + 3] += a * w.w;
        }
    }
    const float* snode = node_scalars + (size_t)n * 32;
    for (int j = 0; j < 32; j++) {
        float sv = snode[j];
        const float* w2r = &sm[K1_OFF_W2S + (128 + j) * 32];
#pragma unroll
        for (int kg = 0; kg < 8; kg++) {
            float4 w = ld4(w2r + kg * 4);
            os[kg * 4 + 0] += sv * w.x; os[kg * 4 + 1] += sv * w.y;
            os[kg * 4 + 2] += sv * w.z; os[kg * 4 + 3] += sv * w.w;
        }
    }
    float* orow = out + (size_t)n * 128;
#pragma unroll
    for (int k = 0; k < 32; k++) orow[k] = os[k] * 0.07905694150420949f; // 1/sqrt(160)

    // gates: sigmoid(x_s[128+o]) -> global scratch
    float* gg = g_gates + (size_t)n * 64;
    for (int o = 0; o < 64; o++) {
        const float* wr = &sm[K1_OFF_W1ST + (128 + o) * 64];
        float acc0 = 0.f, acc1 = 0.f, acc2 = 0.f, acc3 = 0.f;
#pragma unroll
        for (int i = 0; i < 64; i += 4) {
            float4 w = ld4(wr + i);
            acc0 += as[i] * w.x;  acc1 += as[i + 1] * w.y;
            acc2 += as[i + 2] * w.z; acc3 += as[i + 3] * w.w;
        }
        gg[o] = sigmoidf_((acc0 + acc1 + acc2 + acc3) * 0.125f);
    }
}

// ---------------- node kernel K2: vector path, thread = (node, component) ----------------
// smem layout (floats):
//   [0,4096)    W1vT : W1vT[o*64+m] = lin1_w_v[m*64+o]   (64 rows of 64)
//   [4096,7168) W2v  : lin2_w_v row-major (96x32)
#define K2_OFF_W1VT 0
#define K2_OFF_W2V  4096
#define K2_SMEM_FLOATS 7168

__global__ __launch_bounds__(128) void node_vector_kernel(
    const float* __restrict__ node_vectors,
    const float* __restrict__ l1v, const float* __restrict__ l2v,
    float* __restrict__ out,
    int N)
{
    extern __shared__ float sm[];
    for (int i = threadIdx.x; i < 4096; i += blockDim.x) {
        int o = i >> 6, m = i & 63;
        sm[K2_OFF_W1VT + i] = l1v[m * 64 + o];
    }
    for (int i = threadIdx.x; i < 3072; i += blockDim.x) sm[K2_OFF_W2V + i] = l2v[i];
    __syncthreads();

    int idx = blockIdx.x * blockDim.x + threadIdx.x;
    if (idx >= 3 * N) return;
    int n = idx / 3;
    int c = idx - 3 * n;

    const float* agg_n = g_agg + (size_t)n * 256;
    const float* gg = g_gates + (size_t)n * 64;

    float avc[64];
#pragma unroll
    for (int ch = 0; ch < 64; ch++) avc[ch] = agg_n[64 + ch * 3 + c];

    float ov[32];
#pragma unroll
    for (int k = 0; k < 32; k++) ov[k] = 0.f;

    for (int o = 0; o < 64; o++) {
        const float* wr = &sm[K2_OFF_W1VT + o * 64];
        float acc0 = 0.f, acc1 = 0.f, acc2 = 0.f, acc3 = 0.f;
#pragma unroll
        for (int m = 0; m < 64; m += 4) {
            float4 w = ld4(wr + m);
            acc0 += avc[m] * w.x;  acc1 += avc[m + 1] * w.y;
            acc2 += avc[m + 2] * w.z; acc3 += avc[m + 3] * w.w;
        }
        float xv = (acc0 + acc1 + acc2 + acc3) * 0.125f;
        float g = gg[o] * xv;
        const float* w2r = &sm[K2_OFF_W2V + o * 32];
#pragma unroll
        for (int kg = 0; kg < 8; kg++) {
            float4 w = ld4(w2r + kg * 4);
            ov[kg * 4 + 0] += g * w.x; ov[kg * 4 + 1] += g * w.y;
            ov[kg * 4 + 2] += g * w.z; ov[kg * 4 + 3] += g * w.w;
        }
    }
    const float* vnode = node_vectors + (size_t)n * 96;
    for (int j = 0; j < 32; j++) {
        float vv = vnode[3 * j + c];
        const float* w2r = &sm[K2_OFF_W2V + (64 + j) * 32];
#pragma unroll
        for (int kg = 0; kg < 8; kg++) {
            float4 w = ld4(w2r + kg * 4);
            ov[kg * 4 + 0] += vv * w.x; ov[kg * 4 + 1] += vv * w.y;
            ov[kg * 4 + 2] += vv * w.z; ov[kg * 4 + 3] += vv * w.w;
        }
    }
    float* orow = out + (size_t)n * 128;
#pragma unroll
    for (int k = 0; k < 32; k++)
        orow[32 + k * 3 + c] = ov[k] * 0.10206207261596577f; // 1/sqrt(96)
}

// ---------------- launch ----------------
extern "C" void kernel_launch(void* const* d_in, const int* in_sizes, int n_in,
                              void* d_out, int out_size)
{
    const float* node_scalars = (const float*)d_in[0];
    const float* node_vectors = (const float*)d_in[1];
    const float* sh           = (const float*)d_in[2];
    const float* norm         = (const float*)d_in[3];
    const float* w1           = (const float*)d_in[4];
    const float* b1           = (const float*)d_in[5];
    const float* w2           = (const float*)d_in[6];
    const float* b2           = (const float*)d_in[7];
    const float* w3           = (const float*)d_in[8];
    const float* b3           = (const float*)d_in[9];
    const float* l1s          = (const float*)d_in[10];
    const float* l1v          = (const float*)d_in[11];
    const float* l2s          = (const float*)d_in[12];
    const float* l2v          = (const float*)d_in[13];
    const int*   senders      = (const int*)d_in[14];
    const int*   receivers    = (const int*)d_in[15];
    float* out = (float*)d_out;

    int N = in_sizes[0] / MUL;   // node_scalars (N, 32)
    int E = in_sizes[2] / 4;     // sh (E, 4)
    if (N > NMAX) N = NMAX;
    if (E > EMAX) E = EMAX;

    cudaFuncSetAttribute(lut_kernel, cudaFuncAttributeMaxDynamicSharedMemorySize,
                         LUT_SMEM_FLOATS * 4);
    cudaFuncSetAttribute(node_scalar_kernel, cudaFuncAttributeMaxDynamicSharedMemorySize,
                         K1_SMEM_FLOATS * 4);
    cudaFuncSetAttribute(node_vector_kernel, cudaFuncAttributeMaxDynamicSharedMemorySize,
                         K2_SMEM_FLOATS * 4);

    int nb = (N + 1023) / 1024;

    // LUT build first (independent of CSR) so it overlaps the CSR phase
    lut_kernel<<<(LUTN + 1 + 255) / 256, 256, LUT_SMEM_FLOATS * 4>>>(
        w1, b1, w2, b2, w3, b3);

    void* degptr = nullptr;
    cudaGetSymbolAddress(&degptr, g_deg);
    cudaMemsetAsync(degptr, 0, NMAX * sizeof(int));

    count_deg_kernel<<<(E + 255) / 256, 256>>>(receivers, E);
    scan1_kernel<<<nb, 1024>>>(N);
    scan2_kernel<<<1, 32>>>(nb, N);
    scan3_kernel<<<nb, 1024>>>(N);
    scatter_kernel<<<(E + 255) / 256, 256>>>(receivers, E);

    gather_kernel<<<(N + 7) / 8, 256>>>(
        node_scalars, node_vectors, sh, norm, senders, N);

    node_scalar_kernel<<<(N + 127) / 128, 128, K1_SMEM_FLOATS * 4>>>(
        node_scalars, l1s, l2s, out, N);

    node_vector_kernel<<<(3 * N + 127) / 128, 128, K2_SMEM_FLOATS * 4>>>(
        node_vectors, l1v, l2v, out, N);
}